// round 1
// baseline (speedup 1.0000x reference)
#include <cuda_runtime.h>
#include <math.h>

#define NN 100000
#define RR 4
#define EE 200000
#define HD 512     // H * HID (feature width of every layer's per-relation output)
#define HH 8       // heads
#define OD 64      // output dim per head (final layer)

// ---------------- scratch (device globals; zero-initialized at load) ----------------
__device__ float g_h  [(size_t)NN * HD];  // layer input (layers 1,2)
__device__ float g_f  [(size_t)NN * HD];  // per-relation GEMM output
__device__ float g_out[(size_t)NN * HD];  // per-relation aggregation (atomics); re-zeroed each use
__device__ float g_acc[(size_t)NN * HD];  // sum_r elu(out_r); re-zeroed each use
__device__ float g_el [NN * HH];
__device__ float g_er [NN * HH];
__device__ float g_m  [NN * HH];
__device__ float g_den[NN * HH];
__device__ float g_e  [EE * HH];          // edge scores, then exp()

// ---------------- SGEMM: C(g_f)[M=NN, 512] = A[M,K] @ B[K,512] ----------------
// classic 128x128 tile, BK=8, 256 threads, 8x8 per-thread microtile
__global__ __launch_bounds__(256) void sgemm_k(const float* __restrict__ A,
                                               const float* __restrict__ B,
                                               int K, int useGH) {
    if (useGH) A = g_h;
    __shared__ float As[8][128];
    __shared__ float Bs[8][128];
    int tid = threadIdx.x;
    int tx = tid & 15, ty = tid >> 4;
    int rowBase = blockIdx.y * 128;
    int colBase = blockIdx.x * 128;
    int arow = tid >> 1, acol = (tid & 1) * 4;
    int brow = tid >> 5, bcol = (tid & 31) * 4;
    bool arowOK = (rowBase + arow) < NN;
    const float* Ap = A + (size_t)(rowBase + arow) * K + acol;
    const float* Bp = B + (size_t)brow * HD + colBase + bcol;
    float acc[8][8];
#pragma unroll
    for (int i = 0; i < 8; i++)
#pragma unroll
        for (int j = 0; j < 8; j++) acc[i][j] = 0.f;

    for (int kt = 0; kt < K; kt += 8) {
        float4 av = arowOK ? *(const float4*)Ap : make_float4(0.f, 0.f, 0.f, 0.f);
        float4 bv = *(const float4*)Bp;
        Ap += 8;
        Bp += (size_t)8 * HD;
        As[acol + 0][arow] = av.x;
        As[acol + 1][arow] = av.y;
        As[acol + 2][arow] = av.z;
        As[acol + 3][arow] = av.w;
        *(float4*)&Bs[brow][bcol] = bv;
        __syncthreads();
#pragma unroll
        for (int k = 0; k < 8; k++) {
            float a[8], b[8];
#pragma unroll
            for (int i = 0; i < 8; i++) a[i] = As[k][ty * 8 + i];
#pragma unroll
            for (int j = 0; j < 8; j++) b[j] = Bs[k][tx * 8 + j];
#pragma unroll
            for (int i = 0; i < 8; i++)
#pragma unroll
                for (int j = 0; j < 8; j++) acc[i][j] += a[i] * b[j];
        }
        __syncthreads();
    }
#pragma unroll
    for (int i = 0; i < 8; i++) {
        int row = rowBase + ty * 8 + i;
        if (row < NN) {
            float* Crow = g_f + (size_t)row * HD + colBase + tx * 8;
            *(float4*)&Crow[0] = make_float4(acc[i][0], acc[i][1], acc[i][2], acc[i][3]);
            *(float4*)&Crow[4] = make_float4(acc[i][4], acc[i][5], acc[i][6], acc[i][7]);
        }
    }
}

// ---------------- el/er: per (node, head) dot of f row with al/ar ----------------
// 256 threads handle 8 nodes; coalesced smem staging of f rows.
__global__ __launch_bounds__(256) void eler_k(const float* __restrict__ al,
                                              const float* __restrict__ ar) {
    __shared__ float sF[8 * 512];
    __shared__ float sal[512], sar[512];
    int tid = threadIdx.x;
    for (int i = tid; i < 512; i += 256) { sal[i] = al[i]; sar[i] = ar[i]; }
    size_t nodeBase = (size_t)blockIdx.x * 8;
    int navail = NN - (int)nodeBase;
    if (navail > 8) navail = 8;
    const float4* Fv = (const float4*)(g_f + nodeBase * HD);
    float4* sFv = (float4*)sF;
    int tot = navail * 128;
    for (int i = tid; i < 1024; i += 256)
        if (i < tot) sFv[i] = Fv[i];
    __syncthreads();
    int lane = tid & 31;
    int q = lane & 3, h = lane >> 2;
    int nl = tid >> 5;
    float s1 = 0.f, s2 = 0.f;
    int base = nl * 512 + h * 64 + q * 16;
    int cb = h * 64 + q * 16;
#pragma unroll
    for (int i = 0; i < 16; i++) {
        float v = sF[base + i];
        s1 += v * sal[cb + i];
        s2 += v * sar[cb + i];
    }
    s1 += __shfl_xor_sync(0xffffffffu, s1, 1);
    s1 += __shfl_xor_sync(0xffffffffu, s1, 2);
    s2 += __shfl_xor_sync(0xffffffffu, s2, 1);
    s2 += __shfl_xor_sync(0xffffffffu, s2, 2);
    if (q == 0 && nl < navail) {
        g_el[(nodeBase + nl) * HH + h] = s1;
        g_er[(nodeBase + nl) * HH + h] = s2;
    }
}

// ---------------- init m = -inf, den = 0 ----------------
__global__ void init_md_k() {
    int i = blockIdx.x * blockDim.x + threadIdx.x;
    if (i < NN * HH) {
        g_m[i] = -INFINITY;
        g_den[i] = 0.f;
    }
}

__device__ __forceinline__ void atomicMaxF(float* a, float v) {
    if (v >= 0.f) atomicMax((int*)a, __float_as_int(v));
    else atomicMin((unsigned int*)a, __float_as_uint(v));
}

// ---------------- edge score + segment max ----------------
__global__ void edge_max_k(const int* __restrict__ src, const int* __restrict__ dst) {
    int i = blockIdx.x * blockDim.x + threadIdx.x;
    if (i >= EE * HH) return;
    int e = i >> 3, h = i & 7;
    int s = src[e], d = dst[e];
    float v = g_el[s * HH + h] + g_er[d * HH + h];
    v = v > 0.f ? v : 0.2f * v;          // leaky_relu 0.2
    g_e[i] = v;
    atomicMaxF(&g_m[d * HH + h], v);
}

// ---------------- edge exp + segment sum ----------------
__global__ void edge_exp_k(const int* __restrict__ dst) {
    int i = blockIdx.x * blockDim.x + threadIdx.x;
    if (i >= EE * HH) return;
    int e = i >> 3, h = i & 7;
    int d = dst[e];
    float ex = expf(g_e[i] - g_m[d * HH + h]);
    g_e[i] = ex;
    atomicAdd(&g_den[d * HH + h], ex);
}

// ---------------- edge aggregate: out[dst] += f[src] * alpha ----------------
// one warp per edge; float4 gathers, scalar float atomics
__global__ __launch_bounds__(256) void edge_agg_k(const int* __restrict__ src,
                                                  const int* __restrict__ dst) {
    int gw = (blockIdx.x * 256 + threadIdx.x) >> 5;
    int lane = threadIdx.x & 31;
    if (gw >= EE) return;
    int s = src[gw], d = dst[gw];
    float alpha = 0.f;
    if (lane < 8) alpha = g_e[gw * HH + lane] / (g_den[d * HH + lane] + 1e-9f);
    const float4* frow = (const float4*)(g_f + (size_t)s * HD);
    float* orow = g_out + (size_t)d * HD;
#pragma unroll
    for (int j = 0; j < 4; j++) {
        int idx4 = lane + 32 * j;        // float4 index within 512-wide row
        float4 v = frow[idx4];
        float a = __shfl_sync(0xffffffffu, alpha, idx4 >> 4);  // head = (idx4*4)/64
        int c = idx4 * 4;
        atomicAdd(&orow[c + 0], v.x * a);
        atomicAdd(&orow[c + 1], v.y * a);
        atomicAdd(&orow[c + 2], v.z * a);
        atomicAdd(&orow[c + 3], v.w * a);
    }
}

// ---------------- acc += elu(out); out = 0 ----------------
__global__ void elu_acc_k() {
    size_t i = (size_t)blockIdx.x * blockDim.x + threadIdx.x;
    if (i >= (size_t)NN * HD / 4) return;
    float4* o4 = (float4*)g_out;
    float4* a4 = (float4*)g_acc;
    float4 v = o4[i];
    o4[i] = make_float4(0.f, 0.f, 0.f, 0.f);
    float4 a = a4[i];
    a.x += v.x > 0.f ? v.x : expm1f(v.x);
    a.y += v.y > 0.f ? v.y : expm1f(v.y);
    a.z += v.z > 0.f ? v.z : expm1f(v.z);
    a.w += v.w > 0.f ? v.w : expm1f(v.w);
    a4[i] = a;
}

// ---------------- h = acc; acc = 0 (between layers) ----------------
__global__ void copyzero_k() {
    size_t i = (size_t)blockIdx.x * blockDim.x + threadIdx.x;
    if (i >= (size_t)NN * HD / 4) return;
    float4* h4 = (float4*)g_h;
    float4* a4 = (float4*)g_acc;
    h4[i] = a4[i];
    a4[i] = make_float4(0.f, 0.f, 0.f, 0.f);
}

// ---------------- final: mean over heads; acc = 0 ----------------
__global__ void final_k(float* __restrict__ out) {
    int i = blockIdx.x * blockDim.x + threadIdx.x;
    if (i >= NN * OD) return;
    int node = i >> 6, o = i & 63;
    float* base = g_acc + (size_t)node * HD + o;
    float s = 0.f;
#pragma unroll
    for (int h = 0; h < 8; h++) {
        s += base[h * 64];
        base[h * 64] = 0.f;
    }
    out[i] = s * 0.125f;
}

// ---------------- host orchestration ----------------
static void run_layer(const float* inp, int useGH, int K,
                      const float* W, const float* al, const float* ar,
                      const int* src, const int* dst) {
    dim3 gemmGrid(HD / 128, (NN + 127) / 128);
    for (int r = 0; r < RR; r++) {
        sgemm_k<<<gemmGrid, 256>>>(inp, W + (size_t)r * K * HD, K, useGH);
        eler_k<<<(NN + 7) / 8, 256>>>(al + (size_t)r * 512, ar + (size_t)r * 512);
        init_md_k<<<(NN * HH + 255) / 256, 256>>>();
        edge_max_k<<<(EE * HH + 255) / 256, 256>>>(src + (size_t)r * EE, dst + (size_t)r * EE);
        edge_exp_k<<<(EE * HH + 255) / 256, 256>>>(dst + (size_t)r * EE);
        edge_agg_k<<<(EE * 32 + 255) / 256, 256>>>(src + (size_t)r * EE, dst + (size_t)r * EE);
        elu_acc_k<<<(int)(((size_t)NN * HD / 4 + 255) / 256), 256>>>();
    }
}

extern "C" void kernel_launch(void* const* d_in, const int* in_sizes, int n_in,
                              void* d_out, int out_size) {
    const float* x   = (const float*)d_in[0];
    const int*   src = (const int*)d_in[1];
    const int*   dst = (const int*)d_in[2];
    const float* W0  = (const float*)d_in[3];
    const float* al0 = (const float*)d_in[4];
    const float* ar0 = (const float*)d_in[5];
    const float* W1  = (const float*)d_in[6];
    const float* al1 = (const float*)d_in[7];
    const float* ar1 = (const float*)d_in[8];
    const float* W2  = (const float*)d_in[9];
    const float* al2 = (const float*)d_in[10];
    const float* ar2 = (const float*)d_in[11];
    float* out = (float*)d_out;

    int ez = (int)(((size_t)NN * HD / 4 + 255) / 256);

    // layer 0 (input = x, K = 256)
    run_layer(x, 0, 256, W0, al0, ar0, src, dst);
    copyzero_k<<<ez, 256>>>();
    // layer 1 (input = g_h, K = 512)
    run_layer(nullptr, 1, 512, W1, al1, ar1, src, dst);
    copyzero_k<<<ez, 256>>>();
    // layer 2 (input = g_h, K = 512)
    run_layer(nullptr, 1, 512, W2, al2, ar2, src, dst);
    final_k<<<(NN * OD + 255) / 256, 256>>>(out);
}

// round 5
// speedup vs baseline: 1.9613x; 1.9613x over previous
#include <cuda_runtime.h>
#include <cuda_bf16.h>
#include <math.h>
#include <stdint.h>

#define NN 100000
#define RR 4
#define EE 200000
#define HD 512
#define HH 8
#define OD 64

// ---------------- scratch ----------------
__device__ float g_h  [(size_t)NN * HD];
__device__ float g_f4 [(size_t)RR * NN * HD];
__device__ float g_out4[(size_t)RR * NN * HD];
__device__ __nv_bfloat16 g_Ah[(size_t)NN * HD];
__device__ __nv_bfloat16 g_Al[(size_t)NN * HD];
__device__ __nv_bfloat16 g_Bh[(size_t)RR * HD * HD];
__device__ __nv_bfloat16 g_Bl[(size_t)RR * HD * HD];
__device__ float g_el4[RR * NN * HH];
__device__ float g_er4[RR * NN * HH];
__device__ float g_m4 [RR * NN * HH];
__device__ float g_den4[RR * NN * HH];
__device__ float g_e4 [RR * EE * HH];

// ---------------- helpers ----------------
__device__ __forceinline__ uint32_t smem_u32(const void* p) {
    uint32_t a;
    asm("{ .reg .u64 t; cvta.to.shared.u64 t, %1; cvt.u32.u64 %0, t; }" : "=r"(a) : "l"(p));
    return a;
}
__device__ __forceinline__ void split_bf(float v, __nv_bfloat16& h, __nv_bfloat16& l) {
    h = __float2bfloat16(v);
    l = __float2bfloat16(v - __bfloat162float(h));
}
__device__ __forceinline__ void ldm4(uint32_t* r, uint32_t addr) {
    asm volatile("ldmatrix.sync.aligned.m8n8.x4.shared.b16 {%0,%1,%2,%3}, [%4];"
        : "=r"(r[0]), "=r"(r[1]), "=r"(r[2]), "=r"(r[3]) : "r"(addr));
}
__device__ __forceinline__ void mma16816(float* c, const uint32_t* a, uint32_t b0, uint32_t b1) {
    asm volatile("mma.sync.aligned.m16n8k16.row.col.f32.bf16.bf16.f32 "
        "{%0,%1,%2,%3}, {%4,%5,%6,%7}, {%8,%9}, {%0,%1,%2,%3};"
        : "+f"(c[0]), "+f"(c[1]), "+f"(c[2]), "+f"(c[3])
        : "r"(a[0]), "r"(a[1]), "r"(a[2]), "r"(a[3]), "r"(b0), "r"(b1));
}
__device__ __forceinline__ void cp16(uint32_t dst, const void* src, int size) {
    asm volatile("cp.async.ca.shared.global [%0], [%1], 16, %2;"
                 :: "r"(dst), "l"(src), "r"(size));
}
#define CP_COMMIT() asm volatile("cp.async.commit_group;" ::: "memory")
#define CP_WAIT1()  asm volatile("cp.async.wait_group 1;" ::: "memory")

// ---------------- operand conversion ----------------
__global__ void convA_k(const float* __restrict__ X, int K, int useGH) {
    const float* A = useGH ? g_h : X;
    size_t i = (size_t)blockIdx.x * blockDim.x + threadIdx.x;
    size_t tot = (size_t)NN * K / 4;
    if (i >= tot) return;
    float4 v = ((const float4*)A)[i];
    __nv_bfloat16 h0, h1, h2, h3, l0, l1, l2, l3;
    split_bf(v.x, h0, l0); split_bf(v.y, h1, l1);
    split_bf(v.z, h2, l2); split_bf(v.w, h3, l3);
    __nv_bfloat162* Hp = (__nv_bfloat162*)g_Ah;
    __nv_bfloat162* Lp = (__nv_bfloat162*)g_Al;
    __nv_bfloat162 t;
    t.x = h0; t.y = h1; Hp[2 * i] = t;
    t.x = h2; t.y = h3; Hp[2 * i + 1] = t;
    t.x = l0; t.y = l1; Lp[2 * i] = t;
    t.x = l2; t.y = l3; Lp[2 * i + 1] = t;
}

// W[r][k][n] fp32 -> Bh/Bl[r][n][k] bf16 (k contiguous)
__global__ void convW_k(const float* __restrict__ W, int K) {
    __shared__ float t[32][33];
    int r = blockIdx.z;
    const float* Wr = W + (size_t)r * K * HD;
    int n0 = blockIdx.x * 32, k0 = blockIdx.y * 32;
    int tx = threadIdx.x, ty = threadIdx.y;
#pragma unroll
    for (int j = 0; j < 32; j += 8)
        t[ty + j][tx] = Wr[(size_t)(k0 + ty + j) * HD + n0 + tx];
    __syncthreads();
#pragma unroll
    for (int j = 0; j < 32; j += 8) {
        float v = t[tx][ty + j];
        size_t o = (size_t)r * HD * K + (size_t)(n0 + ty + j) * K + k0 + tx;
        __nv_bfloat16 h, l;
        split_bf(v, h, l);
        g_Bh[o] = h;
        g_Bl[o] = l;
    }
}

// ---------------- bf16 split GEMM via mma.sync ----------------
// CTA tile 128x128, K-chunk 32, 512 threads (4x4 warps, 32x32 warp tile)
// smem stage: Ah | Al | Bh | Bl, each 128 rows x 80B (32 bf16 padded to 40)
#define ROWB 80
#define BUFB 10240
#define STAGEB 40960

__device__ __forceinline__ void load_stage(uint32_t sb, int st, int kt,
        const __nv_bfloat16* Bh, const __nv_bfloat16* Bl,
        int rowBase, int colBase, int K, int tid) {
    uint32_t base = sb + st * STAGEB;
#pragma unroll
    for (int i = 0; i < 4; i++) {
        int idx = tid + 512 * i;
        int buf = idx >> 9;
        int within = idx & 511;
        int row = within >> 2;
        int cs = within & 3;
        uint32_t dst = base + buf * BUFB + row * ROWB + cs * 16;
        const __nv_bfloat16* src;
        int size = 16;
        if (buf < 2) {
            int grow = rowBase + row;
            const __nv_bfloat16* P = (buf == 0) ? g_Ah : g_Al;
            if (grow >= NN) { grow = 0; size = 0; }
            src = P + (size_t)grow * K + kt * 32 + cs * 8;
        } else {
            const __nv_bfloat16* P = (buf == 2) ? Bh : Bl;
            src = P + (size_t)(colBase + row) * K + kt * 32 + cs * 8;
        }
        cp16(dst, src, size);
    }
}

__global__ __launch_bounds__(512, 1) void gemm_bf16(int K) {
    int r = blockIdx.z;
    const __nv_bfloat16* Bh = g_Bh + (size_t)r * HD * K;
    const __nv_bfloat16* Bl = g_Bl + (size_t)r * HD * K;
    float* C = g_f4 + (size_t)r * NN * HD;
    int rowBase = blockIdx.y * 128;
    int colBase = blockIdx.x * 128;

    extern __shared__ char smem[];
    uint32_t sb = smem_u32(smem);
    int tid = threadIdx.x;
    int warp = tid >> 5, lane = tid & 31;
    int wm = warp & 3, wn = warp >> 2;
    int lane15 = lane & 15;
    int khalf = (lane >> 4) * 16;

    float acc[2][4][4];
#pragma unroll
    for (int a = 0; a < 2; a++)
#pragma unroll
        for (int b = 0; b < 4; b++)
#pragma unroll
            for (int c = 0; c < 4; c++) acc[a][b][c] = 0.f;

    int nchunks = K >> 5;
    load_stage(sb, 0, 0, Bh, Bl, rowBase, colBase, K, tid);
    CP_COMMIT();

    for (int kt = 0; kt < nchunks; kt++) {
        if (kt + 1 < nchunks)
            load_stage(sb, (kt + 1) & 1, kt + 1, Bh, Bl, rowBase, colBase, K, tid);
        CP_COMMIT();
        CP_WAIT1();
        __syncthreads();
        uint32_t stb = sb + (kt & 1) * STAGEB;
#pragma unroll
        for (int step = 0; step < 2; step++) {
            int kb = step * 32 + khalf;
            uint32_t fah[2][4], fal[2][4], fbh[2][4], fbl[2][4];
#pragma unroll
            for (int mt = 0; mt < 2; mt++) {
                uint32_t ra = stb + (wm * 32 + mt * 16 + lane15) * ROWB + kb;
                ldm4(fah[mt], ra);
                ldm4(fal[mt], ra + BUFB);
            }
#pragma unroll
            for (int nt2 = 0; nt2 < 2; nt2++) {
                uint32_t rb = stb + 2 * BUFB + (wn * 32 + nt2 * 16 + lane15) * ROWB + kb;
                ldm4(fbh[nt2], rb);
                ldm4(fbl[nt2], rb + BUFB);
            }
#pragma unroll
            for (int mt = 0; mt < 2; mt++)
#pragma unroll
                for (int nt = 0; nt < 4; nt++) {
                    int g2 = nt >> 1, o = nt & 1;
                    mma16816(acc[mt][nt], fah[mt], fbh[g2][o], fbh[g2][o + 2]);
                    mma16816(acc[mt][nt], fah[mt], fbl[g2][o], fbl[g2][o + 2]);
                    mma16816(acc[mt][nt], fal[mt], fbh[g2][o], fbh[g2][o + 2]);
                }
        }
        __syncthreads();
    }

    int g = lane >> 2, tg = lane & 3;
#pragma unroll
    for (int mt = 0; mt < 2; mt++)
#pragma unroll
        for (int nt = 0; nt < 4; nt++) {
            int row0 = rowBase + wm * 32 + mt * 16 + g;
            int col = colBase + wn * 32 + nt * 8 + tg * 2;
            if (row0 < NN)
                *(float2*)&C[(size_t)row0 * HD + col] =
                    make_float2(acc[mt][nt][0], acc[mt][nt][1]);
            if (row0 + 8 < NN)
                *(float2*)&C[(size_t)(row0 + 8) * HD + col] =
                    make_float2(acc[mt][nt][2], acc[mt][nt][3]);
        }
}

// ---------------- el/er per (r, node, head) ----------------
__global__ __launch_bounds__(256) void eler_k(const float* __restrict__ al,
                                              const float* __restrict__ ar) {
    int r = blockIdx.y;
    const float* F = g_f4 + (size_t)r * NN * HD;
    __shared__ float sF[8 * 512];
    __shared__ float sal[512], sar[512];
    int tid = threadIdx.x;
    for (int i = tid; i < 512; i += 256) {
        sal[i] = al[r * 512 + i];
        sar[i] = ar[r * 512 + i];
    }
    size_t nodeBase = (size_t)blockIdx.x * 8;
    int navail = NN - (int)nodeBase;
    if (navail > 8) navail = 8;
    const float4* Fv = (const float4*)(F + nodeBase * HD);
    float4* sFv = (float4*)sF;
    int tot = navail * 128;
    for (int i = tid; i < 1024; i += 256)
        if (i < tot) sFv[i] = Fv[i];
    __syncthreads();
    int lane = tid & 31;
    int q = lane & 3, h = lane >> 2;
    int nl = tid >> 5;
    float s1 = 0.f, s2 = 0.f;
    int base = nl * 512 + h * 64 + q * 16;
    int cb = h * 64 + q * 16;
#pragma unroll
    for (int i = 0; i < 16; i++) {
        float v = sF[base + i];
        s1 += v * sal[cb + i];
        s2 += v * sar[cb + i];
    }
    s1 += __shfl_xor_sync(0xffffffffu, s1, 1);
    s1 += __shfl_xor_sync(0xffffffffu, s1, 2);
    s2 += __shfl_xor_sync(0xffffffffu, s2, 1);
    s2 += __shfl_xor_sync(0xffffffffu, s2, 2);
    if (q == 0 && nl < navail) {
        size_t o = ((size_t)r * NN + nodeBase + nl) * HH + h;
        g_el4[o] = s1;
        g_er4[o] = s2;
    }
}

__global__ void init_md_k() {
    int i = blockIdx.x * blockDim.x + threadIdx.x;
    if (i < RR * NN * HH) {
        g_m4[i] = -INFINITY;
        g_den4[i] = 0.f;
    }
}

__device__ __forceinline__ void atomicMaxF(float* a, float v) {
    if (v >= 0.f) atomicMax((int*)a, __float_as_int(v));
    else atomicMin((unsigned int*)a, __float_as_uint(v));
}

__global__ void edge_max_k(const int* __restrict__ src, const int* __restrict__ dst) {
    int i = blockIdx.x * blockDim.x + threadIdx.x;
    if (i >= EE * HH) return;
    int r = blockIdx.y;
    int e = i >> 3, h = i & 7;
    int s = src[r * EE + e], d = dst[r * EE + e];
    float v = g_el4[((size_t)r * NN + s) * HH + h] + g_er4[((size_t)r * NN + d) * HH + h];
    v = v > 0.f ? v : 0.2f * v;
    g_e4[((size_t)r * EE + e) * HH + h] = v;
    atomicMaxF(&g_m4[((size_t)r * NN + d) * HH + h], v);
}

__global__ void edge_exp_k(const int* __restrict__ dst) {
    int i = blockIdx.x * blockDim.x + threadIdx.x;
    if (i >= EE * HH) return;
    int r = blockIdx.y;
    int e = i >> 3, h = i & 7;
    int d = dst[r * EE + e];
    size_t eo = ((size_t)r * EE + e) * HH + h;
    float ex = expf(g_e4[eo] - g_m4[((size_t)r * NN + d) * HH + h]);
    g_e4[eo] = ex;
    atomicAdd(&g_den4[((size_t)r * NN + d) * HH + h], ex);
}

__global__ __launch_bounds__(256) void edge_agg_k(const int* __restrict__ src,
                                                  const int* __restrict__ dst) {
    int gw = (blockIdx.x * 256 + threadIdx.x) >> 5;
    int lane = threadIdx.x & 31;
    if (gw >= EE) return;
    int r = blockIdx.y;
    int s = src[r * EE + gw], d = dst[r * EE + gw];
    float alpha = 0.f;
    if (lane < 8)
        alpha = g_e4[((size_t)r * EE + gw) * HH + lane] /
                (g_den4[((size_t)r * NN + d) * HH + lane] + 1e-9f);
    const float4* frow = (const float4*)(g_f4 + ((size_t)r * NN + s) * HD);
    float* orow = g_out4 + ((size_t)r * NN + d) * HD;
#pragma unroll
    for (int j = 0; j < 4; j++) {
        int idx4 = lane + 32 * j;
        float4 v = frow[idx4];
        float a = __shfl_sync(0xffffffffu, alpha, idx4 >> 4);
        int c = idx4 * 4;
        atomicAdd(&orow[c + 0], v.x * a);
        atomicAdd(&orow[c + 1], v.y * a);
        atomicAdd(&orow[c + 2], v.z * a);
        atomicAdd(&orow[c + 3], v.w * a);
    }
}

__device__ __forceinline__ float elu1(float v) { return v > 0.f ? v : expm1f(v); }

__global__ void combine_k() {
    size_t i = (size_t)blockIdx.x * blockDim.x + threadIdx.x;
    size_t tot = (size_t)NN * HD / 4;
    if (i >= tot) return;
    float4 s = make_float4(0.f, 0.f, 0.f, 0.f);
    float4* o4 = (float4*)g_out4;
#pragma unroll
    for (int r = 0; r < RR; r++) {
        float4 v = o4[(size_t)r * tot + i];
        o4[(size_t)r * tot + i] = make_float4(0.f, 0.f, 0.f, 0.f);
        s.x += elu1(v.x); s.y += elu1(v.y); s.z += elu1(v.z); s.w += elu1(v.w);
    }
    ((float4*)g_h)[i] = s;
}

__global__ void final_k(float* __restrict__ out) {
    int i = blockIdx.x * blockDim.x + threadIdx.x;
    if (i >= NN * OD) return;
    int node = i >> 6, o = i & 63;
    float s = 0.f;
#pragma unroll
    for (int r = 0; r < RR; r++) {
        float* base = g_out4 + ((size_t)r * NN + node) * HD + o;
#pragma unroll
        for (int h = 0; h < 8; h++) {
            float v = base[h * 64];
            base[h * 64] = 0.f;
            s += elu1(v);
        }
    }
    out[i] = s * 0.125f;
}

// ---------------- host ----------------
#define GEMM_SMEM (2 * STAGEB)

static void run_layer(const float* inp, int useGH, int K,
                      const float* W, const float* al, const float* ar,
                      const int* src, const int* dst, int last, float* out) {
    convA_k<<<(int)(((size_t)NN * K / 4 + 255) / 256), 256>>>(inp, K, useGH);
    convW_k<<<dim3(HD / 32, K / 32, RR), dim3(32, 8)>>>(W, K);
    gemm_bf16<<<dim3(HD / 128, (NN + 127) / 128, RR), 512, GEMM_SMEM>>>(K);
    eler_k<<<dim3((NN + 7) / 8, RR), 256>>>(al, ar);
    init_md_k<<<(RR * NN * HH + 255) / 256, 256>>>();
    edge_max_k<<<dim3((EE * HH + 255) / 256, RR), 256>>>(src, dst);
    edge_exp_k<<<dim3((EE * HH + 255) / 256, RR), 256>>>(dst);
    edge_agg_k<<<dim3((EE * 32 + 255) / 256, RR), 256>>>(src, dst);
    if (!last)
        combine_k<<<(int)(((size_t)NN * HD / 4 + 255) / 256), 256>>>();
    else
        final_k<<<(NN * OD + 255) / 256, 256>>>(out);
}

extern "C" void kernel_launch(void* const* d_in, const int* in_sizes, int n_in,
                              void* d_out, int out_size) {
    const float* x   = (const float*)d_in[0];
    const int*   src = (const int*)d_in[1];
    const int*   dst = (const int*)d_in[2];
    const float* W0  = (const float*)d_in[3];
    const float* al0 = (const float*)d_in[4];
    const float* ar0 = (const float*)d_in[5];
    const float* W1  = (const float*)d_in[6];
    const float* al1 = (const float*)d_in[7];
    const float* ar1 = (const float*)d_in[8];
    const float* W2  = (const float*)d_in[9];
    const float* al2 = (const float*)d_in[10];
    const float* ar2 = (const float*)d_in[11];
    float* out = (float*)d_out;

    cudaFuncSetAttribute(gemm_bf16, cudaFuncAttributeMaxDynamicSharedMemorySize, GEMM_SMEM);

    run_layer(x, 0, 256, W0, al0, ar0, src, dst, 0, out);
    run_layer(nullptr, 1, 512, W1, al1, ar1, src, dst, 0, out);
    run_layer(nullptr, 1, 512, W2, al2, ar2, src, dst, 1, out);
}